// round 10
// baseline (speedup 1.0000x reference)
#include <cuda_runtime.h>
#include <cstdint>
#include <math.h>

#define Nn 8
#define Cc 64
#define Hh 256
#define Ww 256
#define HW (Hh*Ww)
#define PTS 8192

// Scratch (__device__ globals per allocation rules)
__device__ float g_x2t[(size_t)Nn * HW * Cc];     // NHWC x2
__device__ float g_x1t[(size_t)Nn * HW * Cc];     // NHWC x1
__device__ float g_fusion[(size_t)Nn * PTS * Cc]; // [p][c] fusion vectors
__device__ int   g_map[(size_t)Nn * HW];          // pixel -> global point idx, -1

// ---------------------------------------------------------------------------
// K1: NCHW->NHWC transpose of BOTH x1 and x2 (float4 both ways) + map init.
// Tile: 32 channels x 128 hw. 256 threads.
// ---------------------------------------------------------------------------
__global__ __launch_bounds__(256) void transpose_kernel(
    const float4* __restrict__ x1, const float4* __restrict__ x2)
{
    __shared__ float t1[32][129];
    __shared__ float t2[32][129];
    const int n   = blockIdx.z;
    const int c0  = blockIdx.y * 32;
    const int hw0 = blockIdx.x * 128;
    const int t = threadIdx.x;
    const int u = t & 7;
    const int j = t >> 3;
    const size_t base4 = (size_t)n * Cc * (HW / 4);

    #pragma unroll
    for (int m = 0; m < 4; m++) {
        int f4i = m * 8 + u;
        size_t idx = base4 + (size_t)(c0 + j) * (HW / 4) + (hw0 >> 2) + f4i;
        float4 v1 = x1[idx];
        float4 v2 = x2[idx];
        t1[j][f4i * 4 + 0] = v1.x; t1[j][f4i * 4 + 1] = v1.y;
        t1[j][f4i * 4 + 2] = v1.z; t1[j][f4i * 4 + 3] = v1.w;
        t2[j][f4i * 4 + 0] = v2.x; t2[j][f4i * 4 + 1] = v2.y;
        t2[j][f4i * 4 + 2] = v2.z; t2[j][f4i * 4 + 3] = v2.w;
    }
    if (blockIdx.y == 0 && t < 128) g_map[(size_t)n * HW + hw0 + t] = -1;
    __syncthreads();

    float4* p1 = (float4*)(g_x1t + (size_t)n * HW * Cc);
    float4* p2 = (float4*)(g_x2t + (size_t)n * HW * Cc);
    #pragma unroll
    for (int v = 0; v < 4; v++) {
        int i = v * 32 + (t >> 3);
        float4 o1, o2;
        o1.x = t1[4 * u + 0][i]; o1.y = t1[4 * u + 1][i];
        o1.z = t1[4 * u + 2][i]; o1.w = t1[4 * u + 3][i];
        o2.x = t2[4 * u + 0][i]; o2.y = t2[4 * u + 1][i];
        o2.z = t2[4 * u + 2][i]; o2.w = t2[4 * u + 3][i];
        size_t po = (size_t)(hw0 + i) * (Cc / 4) + (c0 >> 2) + u;
        p1[po] = o1;
        p2[po] = o2;
    }
}

// ---------------------------------------------------------------------------
// Kmap: scatter point index into per-pixel map. Duplicates: last-writer-wins,
// all duplicates produce identical fusion -> benign.
// ---------------------------------------------------------------------------
__global__ void map_scatter_kernel(const int2* __restrict__ SFL)
{
    int p = blockIdx.x * blockDim.x + threadIdx.x;
    if (p < Nn * PTS) {
        int n = p / PTS;
        int2 sf = SFL[p];
        g_map[(size_t)n * HW + sf.x * Ww + sf.y] = p;
    }
}

// reflect-pad index map for j = p + d - 2 in [-2, H+1]
__device__ __forceinline__ int refl(int j) {
    j = (j < 0) ? -j : j;
    return (j >= Hh) ? (2 * (Hh - 1) - j) : j;
}

// ---------------------------------------------------------------------------
// K2: warp-per-point register-resident attention, fully coalesced I/O.
// Lane layout: half h = l>>4 owns pixels k = 2r+h (r=0..12);
//              channel group cg = 4*(l&15).
// Writes raw fusion vector to g_fusion[p][c] (256B coalesced).
// ---------------------------------------------------------------------------
__global__ __launch_bounds__(256) void attn_kernel(const int2* __restrict__ SFL)
{
    const int p = blockIdx.x * 8 + (threadIdx.x >> 5);
    const int l = threadIdx.x & 31;
    const int n = p / PTS;
    const int2 sf = SFL[p];
    const int ph = sf.x, pw = sf.y;
    const int h  = l >> 4;
    const int cg = (l & 15) * 4;

    int hr[5], wr[5];
    #pragma unroll
    for (int d = 0; d < 5; d++) {
        hr[d] = refl(ph + d - 2);
        wr[d] = refl(pw + d - 2);
    }

    const float* __restrict__ xt = g_x2t + (size_t)n * HW * Cc;

    // xp: coalesced 256B read from NHWC x1t (both halves read same 16 float4s)
    const float4 xp = *(const float4*)(g_x1t + ((size_t)n * HW
                        + (size_t)(ph * Ww + pw)) * Cc + cg);

    // 13 neighbor pixels per lane-half (k=25 aliased to 24, masked below)
    float4 a[13];
    #pragma unroll
    for (int r = 0; r < 13; r++) {
        const int kA = 2 * r;
        const int kB = (2 * r + 1 <= 24) ? (2 * r + 1) : 24;
        int offA = (hr[kA / 5] * Ww + wr[kA % 5]) * Cc;
        int offB = (hr[kB / 5] * Ww + wr[kB % 5]) * Cc;
        int off  = h ? offB : offA;
        a[r] = *(const float4*)(xt + off + cg);
    }

    float e[13], eo[13];
    #pragma unroll
    for (int r = 0; r < 13; r++) {
        float s = xp.x * a[r].x + xp.y * a[r].y + xp.z * a[r].z + xp.w * a[r].w;
        s += __shfl_xor_sync(0xffffffffu, s, 1);
        s += __shfl_xor_sync(0xffffffffu, s, 2);
        s += __shfl_xor_sync(0xffffffffu, s, 4);
        s += __shfl_xor_sync(0xffffffffu, s, 8);
        e[r] = s;
        eo[r] = __shfl_xor_sync(0xffffffffu, s, 16);
    }
    if (h) e[12] = -1e30f; else eo[12] = -1e30f;

    float m = -1e30f;
    #pragma unroll
    for (int r = 0; r < 13; r++) m = fmaxf(m, fmaxf(e[r], eo[r]));
    float sum = 0.f;
    #pragma unroll
    for (int r = 0; r < 13; r++) {
        e[r] = __expf(e[r] - m);
        sum += e[r] + __expf(eo[r] - m);
    }
    const float inv = 1.0f / sum;

    float4 f = make_float4(0.f, 0.f, 0.f, 0.f);
    #pragma unroll
    for (int r = 0; r < 13; r++) {
        float w = e[r] * inv;
        f.x += w * a[r].x;
        f.y += w * a[r].y;
        f.z += w * a[r].z;
        f.w += w * a[r].w;
    }
    f.x += __shfl_xor_sync(0xffffffffu, f.x, 16);
    f.y += __shfl_xor_sync(0xffffffffu, f.y, 16);
    f.z += __shfl_xor_sync(0xffffffffu, f.z, 16);
    f.w += __shfl_xor_sync(0xffffffffu, f.w, 16);

    if (l < 16)
        *(float4*)(g_fusion + (size_t)p * Cc + cg) = f;
}

// ---------------------------------------------------------------------------
// K3: apply. Stream x1t NHWC -> smem transpose -> NCHW out, applying
// (1+a)*v normally or v + a*fusion[map[px]] at sampled pixels. All coalesced.
// Tile: 64 pixels x 64 channels, 256 threads.
// ---------------------------------------------------------------------------
__global__ __launch_bounds__(256) void apply_kernel(
    const float* __restrict__ alpha, float* __restrict__ out)
{
    __shared__ float tile[64][65];
    const int n   = blockIdx.y;
    const int hw0 = blockIdx.x * 64;
    const int t = threadIdx.x;
    const float al = alpha[0];
    const float a1 = 1.0f + al;
    const float* __restrict__ xt = g_x1t + (size_t)n * HW * Cc;
    const int*   __restrict__ mp = g_map + (size_t)n * HW;

    #pragma unroll
    for (int it = 0; it < 4; it++) {
        int idx = it * 256 + t;        // float4 slot 0..1023
        int px  = idx >> 4;            // pixel 0..63
        int c4  = idx & 15;            // float4 within channel row
        int p = mp[hw0 + px];
        float4 v = ((const float4*)(xt + (size_t)(hw0 + px) * Cc))[c4];
        float4 o;
        if (p >= 0) {
            float4 f = ((const float4*)(g_fusion + (size_t)p * Cc))[c4];
            o = make_float4(v.x + al * f.x, v.y + al * f.y,
                            v.z + al * f.z, v.w + al * f.w);
        } else {
            o = make_float4(a1 * v.x, a1 * v.y, a1 * v.z, a1 * v.w);
        }
        tile[c4 * 4 + 0][px] = o.x;
        tile[c4 * 4 + 1][px] = o.y;
        tile[c4 * 4 + 2][px] = o.z;
        tile[c4 * 4 + 3][px] = o.w;
    }
    __syncthreads();

    float4* po = (float4*)(out + (size_t)n * Cc * HW);
    #pragma unroll
    for (int it = 0; it < 4; it++) {
        int idx = it * 256 + t;
        int c = idx >> 4;              // channel 0..63
        int q = idx & 15;              // float4 within 64-px span
        float4 o;
        o.x = tile[c][q * 4 + 0];
        o.y = tile[c][q * 4 + 1];
        o.z = tile[c][q * 4 + 2];
        o.w = tile[c][q * 4 + 3];
        po[(size_t)c * (HW / 4) + (hw0 >> 2) + q] = o;
    }
}

// ---------------------------------------------------------------------------
// SFL passthrough (int -> float) at output tail.
// ---------------------------------------------------------------------------
__global__ void sfl_copy_kernel(const int* __restrict__ SFL,
                                float* __restrict__ dst, int n_elems)
{
    int i = blockIdx.x * blockDim.x + threadIdx.x;
    if (i < n_elems) dst[i] = (float)SFL[i];
}

extern "C" void kernel_launch(void* const* d_in, const int* in_sizes, int n_in,
                              void* d_out, int out_size)
{
    const float* x1    = (const float*)d_in[0];
    const float* x2    = (const float*)d_in[1];
    const int*   SFL   = (const int*)d_in[2];
    const float* alpha = (const float*)d_in[3];
    float* out = (float*)d_out;

    dim3 g1(HW / 128, Cc / 32, Nn);
    transpose_kernel<<<g1, 256>>>((const float4*)x1, (const float4*)x2);

    map_scatter_kernel<<<(Nn * PTS + 255) / 256, 256>>>((const int2*)SFL);

    attn_kernel<<<(Nn * PTS) / 8, 256>>>((const int2*)SFL);

    dim3 g3(HW / 64, Nn);
    apply_kernel<<<g3, 256>>>(alpha, out);

    const int nsfl = in_sizes[2];
    float* dst = out + ((size_t)out_size - (size_t)nsfl);
    sfl_copy_kernel<<<(nsfl + 255) / 256, 256>>>(SFL, dst, nsfl);
}

// round 14
// speedup vs baseline: 1.3856x; 1.3856x over previous
#include <cuda_runtime.h>
#include <cstdint>
#include <math.h>

#define Nn 8
#define Cc 64
#define Hh 256
#define Ww 256
#define HW (Hh*Ww)
#define PTS 8192

// NHWC-transposed copy of x2 (scratch; __device__ global per allocation rules)
__device__ float g_x2t[(size_t)Nn * HW * Cc];

// ---------------------------------------------------------------------------
// Kernel A: fused NCHW->NHWC transpose of x2 + out = (1+alpha)*x1, all float4.
// Proven 74.8us @ 80.7% DRAM — unchanged from R9.
// ---------------------------------------------------------------------------
__global__ __launch_bounds__(256) void prep_kernel(
    const float4* __restrict__ x1, const float4* __restrict__ x2,
    const float* __restrict__ alpha, float4* __restrict__ out)
{
    __shared__ float tile[32][129];
    const int n   = blockIdx.z;
    const int c0  = blockIdx.y * 32;
    const int hw0 = blockIdx.x * 128;
    const float a1 = 1.0f + alpha[0];
    const int t = threadIdx.x;
    const int u = t & 7;
    const int j = t >> 3;
    const size_t base4 = (size_t)n * Cc * (HW / 4);

    #pragma unroll
    for (int m = 0; m < 4; m++) {
        int f4i = m * 8 + u;
        size_t idx = base4 + (size_t)(c0 + j) * (HW / 4) + (hw0 >> 2) + f4i;
        float4 v2 = x2[idx];
        float4 v1 = x1[idx];
        out[idx] = make_float4(a1 * v1.x, a1 * v1.y, a1 * v1.z, a1 * v1.w);
        tile[j][f4i * 4 + 0] = v2.x;
        tile[j][f4i * 4 + 1] = v2.y;
        tile[j][f4i * 4 + 2] = v2.z;
        tile[j][f4i * 4 + 3] = v2.w;
    }
    __syncthreads();

    float4* pt = (float4*)(g_x2t + (size_t)n * HW * Cc);
    #pragma unroll
    for (int v = 0; v < 4; v++) {
        int i = v * 32 + (t >> 3);
        float4 o;
        o.x = tile[4 * u + 0][i];
        o.y = tile[4 * u + 1][i];
        o.z = tile[4 * u + 2][i];
        o.w = tile[4 * u + 3][i];
        pt[(size_t)(hw0 + i) * (Cc / 4) + (c0 >> 2) + u] = o;
    }
}

// reflect-pad index map for j = p + d - 2 in [-2, H+1]
__device__ __forceinline__ int refl(int j) {
    j = (j < 0) ? -j : j;
    return (j >= Hh) ? (2 * (Hh - 1) - j) : j;
}

// ---------------------------------------------------------------------------
// Kernel B: warp-per-point attention, TWO-PASS streaming + ONLINE softmax to
// minimize live registers -> 4 resident blocks (32 warps/SM) for latency
// hiding. Lane layout: half h = l>>4 owns pixels k = 2r+h (r=0..12);
// channel group cg = 4*(l&15). Duplicate points write identical values.
// ---------------------------------------------------------------------------
__global__ __launch_bounds__(256, 4) void attn_kernel(
    const float* __restrict__ x1, const int2* __restrict__ SFL,
    const float* __restrict__ alpha, float* __restrict__ out)
{
    const int p = blockIdx.x * 8 + (threadIdx.x >> 5);
    const int l = threadIdx.x & 31;
    const int n = p / PTS;
    const int2 sf = SFL[p];
    const int ph = sf.x, pw = sf.y;
    const int h  = l >> 4;
    const int cg = (l & 15) * 4;

    int hr[5], wr[5];
    #pragma unroll
    for (int d = 0; d < 5; d++) {
        hr[d] = refl(ph + d - 2);
        wr[d] = refl(pw + d - 2);
    }

    // Per-lane byte offsets for the 13 owned pixels (k=25 aliased to 24,
    // masked in softmax below). Computed once; reused by both passes.
    int offs[13];
    #pragma unroll
    for (int r = 0; r < 13; r++) {
        const int kA = 2 * r;
        const int kB = (2 * r + 1 <= 24) ? (2 * r + 1) : 24;
        int offA = (hr[kA / 5] * Ww + wr[kA % 5]) * Cc;
        int offB = (hr[kB / 5] * Ww + wr[kB % 5]) * Cc;
        offs[r] = h ? offB : offA;
    }

    const float* __restrict__ xt = g_x2t + (size_t)n * HW * Cc + cg;

    // xp: lanes 0-15 load 4 scattered channels from x1, share to upper half.
    float4 xp = make_float4(0.f, 0.f, 0.f, 0.f);
    const size_t b0 = ((size_t)n * Cc + cg) * HW + (size_t)ph * Ww + pw;
    if (l < 16) {
        xp.x = x1[b0];
        xp.y = x1[b0 + HW];
        xp.z = x1[b0 + 2 * HW];
        xp.w = x1[b0 + 3 * HW];
    }
    xp.x += __shfl_xor_sync(0xffffffffu, xp.x, 16);
    xp.y += __shfl_xor_sync(0xffffffffu, xp.y, 16);
    xp.z += __shfl_xor_sync(0xffffffffu, xp.z, 16);
    xp.w += __shfl_xor_sync(0xffffffffu, xp.w, 16);

    // Pass A: energies with online softmax (running max m, running sum).
    float e[13];
    float m = -1e30f, sum = 0.f;
    #pragma unroll
    for (int r = 0; r < 13; r++) {
        const float4 a = *(const float4*)(xt + offs[r]);
        float s = xp.x * a.x + xp.y * a.y + xp.z * a.z + xp.w * a.w;
        s += __shfl_xor_sync(0xffffffffu, s, 1);
        s += __shfl_xor_sync(0xffffffffu, s, 2);
        s += __shfl_xor_sync(0xffffffffu, s, 4);
        s += __shfl_xor_sync(0xffffffffu, s, 8);
        float so = __shfl_xor_sync(0xffffffffu, s, 16);
        if (r == 12) {                 // k=25 doesn't exist
            if (h) s = -1e30f; else so = -1e30f;
        }
        e[r] = s;
        const float nm = fmaxf(m, fmaxf(s, so));
        sum = sum * __expf(m - nm) + __expf(s - nm) + __expf(so - nm);
        m = nm;
    }
    const float inv = 1.0f / sum;

    // Pass B: reload neighbors (L2-hot) and accumulate fusion.
    float4 f = make_float4(0.f, 0.f, 0.f, 0.f);
    #pragma unroll
    for (int r = 0; r < 13; r++) {
        const float4 a = *(const float4*)(xt + offs[r]);
        const float w = __expf(e[r] - m) * inv;
        f.x += w * a.x;
        f.y += w * a.y;
        f.z += w * a.z;
        f.w += w * a.w;
    }
    f.x += __shfl_xor_sync(0xffffffffu, f.x, 16);
    f.y += __shfl_xor_sync(0xffffffffu, f.y, 16);
    f.z += __shfl_xor_sync(0xffffffffu, f.z, 16);
    f.w += __shfl_xor_sync(0xffffffffu, f.w, 16);

    if (l < 16) {
        const float al = alpha[0];
        out[b0]          = xp.x + al * f.x;
        out[b0 + HW]     = xp.y + al * f.y;
        out[b0 + 2 * HW] = xp.z + al * f.z;
        out[b0 + 3 * HW] = xp.w + al * f.w;
    }
}

// ---------------------------------------------------------------------------
// Kernel C: SFL passthrough (int -> float, output dtype) at buffer tail.
// ---------------------------------------------------------------------------
__global__ void sfl_copy_kernel(const int* __restrict__ SFL,
                                float* __restrict__ dst, int n_elems)
{
    int i = blockIdx.x * blockDim.x + threadIdx.x;
    if (i < n_elems) dst[i] = (float)SFL[i];
}

extern "C" void kernel_launch(void* const* d_in, const int* in_sizes, int n_in,
                              void* d_out, int out_size)
{
    const float* x1    = (const float*)d_in[0];
    const float* x2    = (const float*)d_in[1];
    const int*   SFL   = (const int*)d_in[2];
    const float* alpha = (const float*)d_in[3];
    float* out = (float*)d_out;

    dim3 gA(HW / 128, Cc / 32, Nn);
    prep_kernel<<<gA, 256>>>((const float4*)x1, (const float4*)x2, alpha,
                             (float4*)out);

    attn_kernel<<<(Nn * PTS) / 8, 256>>>(x1, (const int2*)SFL, alpha, out);

    const int nsfl = in_sizes[2];
    float* dst = out + ((size_t)out_size - (size_t)nsfl);
    sfl_copy_kernel<<<(nsfl + 255) / 256, 256>>>(SFL, dst, nsfl);
}